// round 6
// baseline (speedup 1.0000x reference)
#include <cuda_runtime.h>
#include <math.h>

#define BB    2048
#define U1N   101
#define DN    128
#define STEPN 165
#define HN    200    // hidden
#define IM1   63     // i-1
#define UPW   13     // u-rows per warp (8 warps x 13 = 104 >= 101)
#define NPAIR 6      // u-pairs per warp; 13th u handled as scalar

// scratch
__device__ float  g_base[BB * HN];
__device__ float2 g_W1dup[DN][224];     // (W1e[k][o], W1e[k][o]) dup-packed, o>=200 zero
__device__ int    g_mask_is_i32;

// f32x2 packed helpers (sm_100+; ptxas never emits these from C++)
#define FMA2(d, a, b) \
    asm("fma.rn.f32x2 %0, %1, %2, %0;" : "+l"(d) : "l"(a), "l"(b))
#define PACK2(d, lo, hi) \
    asm("mov.b64 %0, {%1, %2};" : "=l"(d) : "f"(lo), "f"(hi))
#define UNPACK2(lo, hi, d) \
    asm("mov.b64 {%0, %1}, %2;" : "=f"(lo), "=f"(hi) : "l"(d))

// ---------------------------------------------------------------------------
__global__ void flag_init_kernel() { g_mask_is_i32 = 1; }

__global__ __launch_bounds__(256) void mask_detect_kernel(const unsigned* __restrict__ m)
{
    int n = (BB * U1N) / 4;
    for (int idx = blockIdx.x * 256 + threadIdx.x; idx < n; idx += gridDim.x * 256) {
        if (m[idx] > 1u) { atomicExch(&g_mask_is_i32, 0); return; }
    }
}

__global__ __launch_bounds__(256) void w1dup_kernel(const float* __restrict__ W1)
{
    int idx = blockIdx.x * 256 + threadIdx.x;
    if (idx < DN * 224) {
        int k = idx / 224, o = idx % 224;
        float v = (o < HN) ? W1[(size_t)(130 + k) * HN + o] : 0.f;
        g_W1dup[k][o] = make_float2(v, v);
    }
}

// ---------------------------------------------------------------------------
// Kernel 1: per-b reductions + step_context + base.  512 threads.
// ---------------------------------------------------------------------------
__global__ __launch_bounds__(512) void prep_kernel(
    const float* __restrict__ emb, const float* __restrict__ W_sc,
    const float* __restrict__ b_sc, const float* __restrict__ W1,
    const float* __restrict__ b1, const int* __restrict__ seq)
{
    int b   = blockIdx.x;
    int tid = threadIdx.x;
    int q   = tid & 31;          // float4 column (d = 4q..4q+3)
    int h   = tid >> 5;          // 0..15 row-split group

    __shared__ float4 p4_emb[16][32], p4_hist[16][32], p4_sel[16][32];
    __shared__ float  s_minc[128], s_memb[128], s_mhist[128], s_msel[128], s_sc[128];
    __shared__ float  s_scp[2][128];
    __shared__ float  s_bp[2][200];

    const float4* eb4 = (const float4*)(emb + (size_t)b * STEPN * DN);
    const float4* e4  = (const float4*)emb;

    float4 se = make_float4(0.f, 0.f, 0.f, 0.f);
    float4 sh = se, ss = se;
    #pragma unroll 2
    for (int t = h; t < STEPN; t += 16) {
        float4 v = eb4[t * 32 + q];
        se.x += v.x; se.y += v.y; se.z += v.z; se.w += v.w;
    }
    for (int t = 101 + h; t < 164; t += 16) {
        float4 v = eb4[t * 32 + q];
        sh.x += v.x; sh.y += v.y; sh.z += v.z; sh.w += v.w;
    }
    for (int j = h; j < IM1; j += 16) {
        int s = seq[b * IM1 + j];
        float4 v = e4[((size_t)b * IM1 + s) * 32 + q];   // deliberate cross-batch flat gather
        ss.x += v.x; ss.y += v.y; ss.z += v.z; ss.w += v.w;
    }
    if (h == 0) ((float4*)s_minc)[q] = eb4[164 * 32 + q];
    p4_emb[h][q] = se; p4_hist[h][q] = sh; p4_sel[h][q] = ss;
    __syncthreads();

    if (tid < 128) {
        int d = tid;
        const float* pe = (const float*)p4_emb;
        const float* ph = (const float*)p4_hist;
        const float* ps = (const float*)p4_sel;
        float ae = 0.f, ah = 0.f, as = 0.f;
        #pragma unroll
        for (int g = 0; g < 16; ++g) {
            ae += pe[g * 128 + d]; ah += ph[g * 128 + d]; as += ps[g * 128 + d];
        }
        s_memb[d]  = ae * (1.f / STEPN);
        s_mhist[d] = ah * (1.f / IM1);
        s_msel[d]  = as * (1.f / IM1);
    }
    __syncthreads();

    // step_context partials: g=0 over msel/W_sc[0:128), g=1 over mhist/W_sc[128:256)
    if (tid < 256) {
        int g = tid >> 7, d = tid & 127;
        const float* vsrc = g ? s_mhist : s_msel;
        const float* wsrc = W_sc + (size_t)(g ? 128 : 0) * 128;
        float a0 = 0.f, a1 = 0.f;
        #pragma unroll 4
        for (int k = 0; k < 128; k += 2) {
            a0 = fmaf(vsrc[k],     wsrc[(k)     * 128 + d], a0);
            a1 = fmaf(vsrc[k + 1], wsrc[(k + 1) * 128 + d], a1);
        }
        s_scp[g][d] = a0 + a1;
    }
    __syncthreads();
    if (tid < 128) s_sc[tid] = s_scp[0][tid] + s_scp[1][tid] + b_sc[tid];
    __syncthreads();

    // base partials: g2=0: b1 + idx + minc@W1[2:130] + sc[0:64)@W1[258:322)
    //                g2=1: sc[64:128)@W1[322:386) + memb@W1[386:514)
    {
        int o = tid & 255, g2 = tid >> 8;
        if (o < HN) {
            float a0, a1 = 0.f;
            if (g2 == 0) {
                a0 = b1[o] + 0.5f * W1[HN + o];
                #pragma unroll 2
                for (int k = 0; k < 128; k += 2) {
                    a0 = fmaf(s_minc[k],     W1[(size_t)(2 + k) * HN + o], a0);
                    a1 = fmaf(s_minc[k + 1], W1[(size_t)(3 + k) * HN + o], a1);
                }
                #pragma unroll 2
                for (int k = 0; k < 64; ++k)
                    a0 = fmaf(s_sc[k], W1[(size_t)(258 + k) * HN + o], a0);
            } else {
                a0 = 0.f;
                #pragma unroll 2
                for (int k = 64; k < 128; ++k)
                    a0 = fmaf(s_sc[k], W1[(size_t)(258 + k) * HN + o], a0);
                #pragma unroll 2
                for (int k = 0; k < 128; k += 2) {
                    a0 = fmaf(s_memb[k],     W1[(size_t)(386 + k) * HN + o], a0);
                    a1 = fmaf(s_memb[k + 1], W1[(size_t)(387 + k) * HN + o], a1);
                }
            }
            s_bp[g2][o] = a0 + a1;
        }
    }
    __syncthreads();
    if (tid < HN) g_base[b * HN + tid] = s_bp[0][tid] + s_bp[1][tid];
}

// ---------------------------------------------------------------------------
// Kernel 2: pi[b,u] = relu(base + w*W1r0 + emb_u @ W1e) @ W2 + b2, then
// mask + log_softmax + argmax.  8 warps, 13 u/warp (6 f32x2 pairs + 1 scalar),
// W1e read dup-packed from g_W1dup, 2 blocks/SM.
// ---------------------------------------------------------------------------
__global__ __launch_bounds__(256, 2) void main_kernel(
    const float* __restrict__ emb, const float* __restrict__ w,
    const float* __restrict__ W1, const float* __restrict__ W2,
    const float* __restrict__ b2, const void* __restrict__ mask,
    float* __restrict__ out, int mode)
{
    int b    = blockIdx.x;
    int tid  = threadIdx.x;
    int lane = tid & 31;
    int wid  = tid >> 5;

    __shared__ float s_base[224], s_w1r0[224], s_w2[224];
    __shared__ float s_w[112];
    __shared__ float s_pi[128];
    __shared__ __align__(16) float2 s_eT[8][64][NPAIR];   // [warp][k][u-pair]
    __shared__ float s_eS[8][64];                          // scalar 13th u
    __shared__ float s_lse;
    __shared__ int   s_sel;

    for (int o = tid; o < 224; o += 256) {
        s_base[o] = (o < HN) ? g_base[b * HN + o] : 0.f;
        s_w1r0[o] = (o < HN) ? W1[o]              : 0.f;
        s_w2[o]   = (o < HN) ? W2[o]              : 0.f;
    }
    for (int u = tid; u < 112; u += 256) s_w[u] = (u < U1N) ? w[b * U1N + u] : 0.f;
    __syncthreads();

    float bb2 = b2[0];
    int u0 = wid * UPW;                 // 0,13,...,91

    // accumulators: pairs (u0+2up, u0+2up+1) and scalar u0+12
    unsigned long long acc[NPAIR][7];
    float accs[7];
    {
        float ws = s_w[u0 + 12];
        #pragma unroll
        for (int up = 0; up < NPAIR; ++up) {
            float w_lo = s_w[u0 + 2 * up];
            float w_hi = s_w[u0 + 2 * up + 1];
            #pragma unroll
            for (int j = 0; j < 7; ++j) {
                int o = lane + 32 * j;
                float i_lo = s_base[o] + w_lo * s_w1r0[o];
                float i_hi = s_base[o] + w_hi * s_w1r0[o];
                PACK2(acc[up][j], i_lo, i_hi);
            }
        }
        #pragma unroll
        for (int j = 0; j < 7; ++j) {
            int o = lane + 32 * j;
            accs[j] = s_base[o] + ws * s_w1r0[o];
        }
    }

    for (int h0 = 0; h0 < DN; h0 += 64) {
        // stage transposed e: s_eT[wid][k][up] = (emb[u0+2up][h0+k], emb[u0+2up+1][h0+k])
        __syncwarp();
        #pragma unroll
        for (int ul = 0; ul < UPW; ++ul) {
            const float2 ev = *(const float2*)(emb +
                ((size_t)b * STEPN + (u0 + ul)) * DN + h0 + 2 * lane);
            if (ul < 12) {
                float* p = (float*)&s_eT[wid][2 * lane][ul >> 1] + (ul & 1);
                p[0]             = ev.x;
                p[2 * NPAIR]     = ev.y;      // next k slot: NPAIR float2 = 12 floats
            } else {
                s_eS[wid][2 * lane]     = ev.x;
                s_eS[wid][2 * lane + 1] = ev.y;
            }
        }
        __syncwarp();

        #pragma unroll 2
        for (int k = 0; k < 64; ++k) {
            // e pairs: 3x LDS.128 + scalar LDS.32 (broadcast reads)
            uint4 e01 = *(const uint4*)&s_eT[wid][k][0];
            uint4 e23 = *(const uint4*)&s_eT[wid][k][2];
            uint4 e45 = *(const uint4*)&s_eT[wid][k][4];
            float es  = s_eS[wid][k];
            unsigned long long ep[NPAIR];
            ep[0] = ((unsigned long long)e01.y << 32) | e01.x;
            ep[1] = ((unsigned long long)e01.w << 32) | e01.z;
            ep[2] = ((unsigned long long)e23.y << 32) | e23.x;
            ep[3] = ((unsigned long long)e23.w << 32) | e23.z;
            ep[4] = ((unsigned long long)e45.y << 32) | e45.x;
            ep[5] = ((unsigned long long)e45.w << 32) | e45.z;

            const float2* wrow = &g_W1dup[h0 + k][lane];
            float2 wd[7];
            #pragma unroll
            for (int j = 0; j < 7; ++j) wd[j] = wrow[32 * j];

            #pragma unroll
            for (int j = 0; j < 7; ++j) {
                unsigned long long wdu = *(unsigned long long*)&wd[j];
                #pragma unroll
                for (int up = 0; up < NPAIR; ++up)
                    FMA2(acc[up][j], ep[up], wdu);
                accs[j] = fmaf(es, wd[j].x, accs[j]);
            }
        }
    }

    // epilogue: relu, dot W2, warp reduce; 13 pi per warp
    #pragma unroll
    for (int up = 0; up < NPAIR; ++up) {
        float s0 = 0.f, s1 = 0.f;
        #pragma unroll
        for (int j = 0; j < 7; ++j) {
            float a_lo, a_hi;
            UNPACK2(a_lo, a_hi, acc[up][j]);
            float w2v = s_w2[lane + 32 * j];
            s0 += fmaxf(a_lo, 0.f) * w2v;
            s1 += fmaxf(a_hi, 0.f) * w2v;
        }
        #pragma unroll
        for (int off = 16; off; off >>= 1) {
            s0 += __shfl_xor_sync(0xffffffffu, s0, off);
            s1 += __shfl_xor_sync(0xffffffffu, s1, off);
        }
        if (lane == 0) {
            int ue = u0 + 2 * up, uo = ue + 1;
            if (ue < U1N) s_pi[ue] = s0 + bb2;
            if (uo < U1N) s_pi[uo] = s1 + bb2;
        }
    }
    {
        float s = 0.f;
        #pragma unroll
        for (int j = 0; j < 7; ++j)
            s += fmaxf(accs[j], 0.f) * s_w2[lane + 32 * j];
        #pragma unroll
        for (int off = 16; off; off >>= 1)
            s += __shfl_xor_sync(0xffffffffu, s, off);
        if (lane == 0 && (u0 + 12) < U1N) s_pi[u0 + 12] = s + bb2;
    }
    __syncthreads();

    // mask (dtype-adaptive: int32 vs byte layout)
    if (tid < U1N) {
        bool mv;
        if (g_mask_is_i32)
            mv = ((const int*)mask)[b * U1N + tid] != 0;
        else
            mv = ((const unsigned char*)mask)[b * U1N + tid] != 0;
        if (mv) s_pi[tid] = -1000000.0f;
    }
    __syncthreads();

    // log_softmax + argmax (warp 0)
    if (wid == 0) {
        float mv = -3.4e38f; int mi = U1N;
        for (int u = lane; u < U1N; u += 32) {
            float v = s_pi[u];
            if (v > mv) { mv = v; mi = u; }
        }
        #pragma unroll
        for (int off = 16; off; off >>= 1) {
            float ov = __shfl_xor_sync(0xffffffffu, mv, off);
            int   oi = __shfl_xor_sync(0xffffffffu, mi, off);
            if (ov > mv || (ov == mv && oi < mi)) { mv = ov; mi = oi; }
        }
        float se = 0.f;
        for (int u = lane; u < U1N; u += 32) se += expf(s_pi[u] - mv);
        #pragma unroll
        for (int off = 16; off; off >>= 1)
            se += __shfl_xor_sync(0xffffffffu, se, off);
        if (lane == 0) { s_lse = mv + logf(se); s_sel = mi; }
    }
    __syncthreads();

    float lse = s_lse;
    if (mode == 0) {                 // p only
        for (int u = tid; u < U1N; u += 256)
            out[b * U1N + u] = s_pi[u] - lse;
    } else if (mode == 1) {          // [selected (as float) | p]
        if (tid == 0) out[b] = (float)s_sel;
        float* op = out + BB;
        for (int u = tid; u < U1N; u += 256)
            op[b * U1N + u] = s_pi[u] - lse;
    } else {                         // selected only (int32)
        if (tid == 0) ((int*)out)[b] = s_sel;
    }
}

// ---------------------------------------------------------------------------
extern "C" void kernel_launch(void* const* d_in, const int* in_sizes, int n_in,
                              void* d_out, int out_size)
{
    const float* emb  = (const float*)d_in[0];   // (B, STEP, D)
    const float* w    = (const float*)d_in[1];   // (B, U1)
    const float* W_sc = (const float*)d_in[2];   // (256, 128)
    const float* b_sc = (const float*)d_in[3];   // (128)
    const float* W1   = (const float*)d_in[4];   // (514, 200)
    const float* b1   = (const float*)d_in[5];   // (200)
    const float* W2   = (const float*)d_in[6];   // (200, 1)
    const float* b2   = (const float*)d_in[7];   // (1)
    const int*   seq  = (const int*)d_in[8];     // (B, 63)
    const void*  mask = d_in[9];                 // (B, U1) bool (byte or i32)

    int mode = 1;                                  // default: selected + p
    if (out_size == BB * U1N) mode = 0;            // p only
    else if (out_size == BB)  mode = 2;            // selected only

    flag_init_kernel<<<1, 1>>>();
    mask_detect_kernel<<<208, 256>>>((const unsigned*)mask);
    w1dup_kernel<<<(DN * 224 + 255) / 256, 256>>>(W1);
    prep_kernel<<<BB, 512>>>(emb, W_sc, b_sc, W1, b1, seq);
    main_kernel<<<BB, 256>>>(emb, w, W1, W2, b2, mask, (float*)d_out, mode);
}